// round 14
// baseline (speedup 1.0000x reference)
#include <cuda_runtime.h>
#include <cuda_bf16.h>

#define E_ 64
#define A_ 8
#define L_ 2048
#define D_ 128
#define H_ 8
#define EA_ (E_*A_)
#define CHUNK_ 256
#define NC_ 8

typedef unsigned long long ull;

// ---------------- device scratch ----------------
__device__ float g_Wq_eff[386 * 128];
__device__ float g_Wk_eff[128 * 128];
__device__ float g_Wv_eff[129 * 128];
__device__ float g_wtil [EA_ * H_ * 128];
__device__ float g_pu[EA_ * NC_ * 1024];
__device__ float g_pm[EA_ * NC_ * 8];
__device__ float g_pd[EA_ * NC_ * 8];
__device__ int   g_cnt[EA_];

// ---------------- packed f32x2 helpers ----------
__device__ __forceinline__ ull pack2(float a, float b) {
    ull r; asm("mov.b64 %0, {%1, %2};" : "=l"(r)
               : "r"(__float_as_uint(a)), "r"(__float_as_uint(b)));
    return r;
}
__device__ __forceinline__ void unpack2(ull v, float& a, float& b) {
    unsigned int x, y;
    asm("mov.b64 {%0, %1}, %2;" : "=r"(x), "=r"(y) : "l"(v));
    a = __uint_as_float(x); b = __uint_as_float(y);
}
__device__ __forceinline__ ull fma2(ull a, ull b, ull c) {
    ull d; asm("fma.rn.f32x2 %0, %1, %2, %3;" : "=l"(d) : "l"(a), "l"(b), "l"(c));
    return d;
}
__device__ __forceinline__ ull mul2(ull a, ull b) {
    ull d; asm("mul.rn.f32x2 %0, %1, %2;" : "=l"(d) : "l"(a), "l"(b));
    return d;
}
__device__ __forceinline__ void cp_async16(unsigned int saddr, const void* g) {
    asm volatile("cp.async.cg.shared.global [%0], [%1], 16;" :: "r"(saddr), "l"(g));
}
__device__ __forceinline__ void cp_commit() { asm volatile("cp.async.commit_group;"); }
__device__ __forceinline__ void cp_wait3()  { asm volatile("cp.async.wait_group 3;"); }

// ---------------- setup 1: compose projection matrices -------------------
__global__ void setup_eff(const float* __restrict__ Wq_proj,
                          const float* __restrict__ Wk_proj,
                          const float* __restrict__ Wv_proj,
                          const float* __restrict__ Wq,
                          const float* __restrict__ Wk,
                          const float* __restrict__ Wv) {
    __shared__ float row[128];
    int r = blockIdx.x, t = threadIdx.x;
    const float* proj; const float* W; float* out;
    if (r < 386)      { proj = Wq_proj + r * 128;        W = Wq; out = g_Wq_eff + r * 128; }
    else if (r < 514) { proj = Wk_proj + (r - 386) * 128; W = Wk; out = g_Wk_eff + (r - 386) * 128; }
    else              { proj = Wv_proj + (r - 514) * 128; W = Wv; out = g_Wv_eff + (r - 514) * 128; }
    row[t] = proj[t];
    __syncthreads();
    int h = t >> 4, k = t & 15;
    const float* Wb = W + h * 2048 + k;
    float a0 = 0.f, a1 = 0.f, a2 = 0.f, a3 = 0.f;
    #pragma unroll 8
    for (int m = 0; m < 128; m += 4) {
        a0 += row[m]     * __ldg(Wb + m * 16);
        a1 += row[m + 1] * __ldg(Wb + (m + 1) * 16);
        a2 += row[m + 2] * __ldg(Wb + (m + 2) * 16);
        a3 += row[m + 3] * __ldg(Wb + (m + 3) * 16);
    }
    out[t] = (a0 + a1) + (a2 + a3);
}

// ---------------- setup 2: per-(e,a) query -> w-tilde + cnt reset --------
__global__ void setup_wtil(const float* __restrict__ gc,
                           const float* __restrict__ dep,
                           const float* __restrict__ tbd,
                           const float* __restrict__ loadv) {
    __shared__ float qin[386];
    __shared__ float qh[128];
    int ea = blockIdx.x, t = threadIdx.x;
    int e = ea >> 3, a = ea & 7;
    qin[t]       = gc [e * 128 + t];
    qin[128 + t] = dep[e * 128 + t];
    qin[256 + t] = tbd[e * 128 + t];
    if (t == 0) { qin[384] = loadv[e * 8 + a]; qin[385] = (float)a; g_cnt[ea] = 0; }
    __syncthreads();
    float a0 = 0.f, a1 = 0.f, a2 = 0.f, a3 = 0.f;
    #pragma unroll 4
    for (int j = 0; j < 384; j += 4) {
        a0 += qin[j]     * g_Wq_eff[j * 128 + t];
        a1 += qin[j + 1] * g_Wq_eff[(j + 1) * 128 + t];
        a2 += qin[j + 2] * g_Wq_eff[(j + 2) * 128 + t];
        a3 += qin[j + 3] * g_Wq_eff[(j + 3) * 128 + t];
    }
    a0 += qin[384] * g_Wq_eff[384 * 128 + t];
    a1 += qin[385] * g_Wq_eff[385 * 128 + t];
    qh[t] = (a0 + a1) + (a2 + a3);
    __syncthreads();
    int d = t;
    #pragma unroll
    for (int h = 0; h < 8; h++) {
        float w = 0.f;
        #pragma unroll
        for (int k = 0; k < 16; k++)
            w += qh[h * 16 + k] * g_Wk_eff[d * 128 + h * 16 + k];
        g_wtil[(ea * 8 + h) * 128 + d] = w * 0.25f;
    }
}

// ---------------- attention partial + fused combine (R13 core) -----------
// Split into 4 sequential launches of 1024 CTAs (pc0 offset) so ncu's
// capture window lands on this kernel. Each ea's 8 chunks stay within one
// launch (split at pc multiples of 8) so the atomic combine is unchanged.
__global__ __launch_bounds__(128, 3)
void attn_part(const float* __restrict__ emb,
               const int*   __restrict__ lens,
               const float* __restrict__ Wo,
               float*       __restrict__ out,
               int pc0) {
    __shared__ __align__(16) char sraw[32 * 1024];  // 4 warps x 4 slots x 2KB
    __shared__ float sm_m[4][8], sm_d[4][8], sm_scale[4][8];
    __shared__ float c_scale[NC_][8], c_den[8];
    __shared__ int s_last;

    int pc = blockIdx.x + pc0;
    int ea = pc >> 3, c = pc & 7;
    int a  = ea & 7;
    int len = lens[ea];
    len = max(1, min(len, L_));
    int c0 = c << 8;
    if (c0 >= len) return;
    int c1 = min(c0 + CHUNK_, len);
    int rows = c1 - c0;
    int nst = (rows + 15) >> 4;
    int nact = min(NC_, (len + CHUNK_ - 1) >> 8);

    int tid  = threadIdx.x;
    int warp = tid >> 5, lane = tid & 31;
    int h = lane >> 2, g = lane & 3;

    float* wbuf = (float*)(sraw + warp * 8192);      // 4 x 2KB slots
    unsigned int sb = (unsigned int)__cvta_generic_to_shared(wbuf);
    const char* base = (const char*)emb + (size_t)ea * (L_ * 512);

    #define ISSUE(S) do {                                                    \
        int s_ = (S);                                                        \
        if (s_ < nst) {                                                      \
            unsigned int sb_ = sb + (unsigned int)((s_ & 3) * 2048);         \
            _Pragma("unroll")                                                \
            for (int j_ = 0; j_ < 4; j_++) {                                 \
                int r_ = min(c0 + s_ * 16 + warp * 4 + j_, c1 - 1);          \
                cp_async16(sb_ + j_ * 512 + lane * 16,                       \
                           base + (size_t)r_ * 512 + lane * 16);             \
            }                                                                \
        }                                                                    \
        cp_commit();                                                         \
    } while (0)

    ull w2[16], u2[16];
    {
        const float* wb = g_wtil + (ea * 8 + h) * 128;
        #pragma unroll
        for (int i = 0; i < 8; i++) {
            ulonglong2 v = *(const ulonglong2*)(wb + i * 16 + g * 4);
            w2[2*i] = v.x; w2[2*i+1] = v.y;
        }
    }
    #pragma unroll
    for (int i = 0; i < 16; i++) u2[i] = 0ull;

    float m = -1e30f;
    float denom = 0.f;

    ISSUE(0); ISSUE(1); ISSUE(2); ISSUE(3);

    for (int s = 0; s < nst; s++) {
        cp_wait3();
        const float* sp0 = wbuf + ((s & 3) << 9);
        int rb = s * 16 + warp * 4;

        #pragma unroll
        for (int jp = 0; jp < 2; jp++) {          // two pairs of rows
            int rl0 = rb + jp * 2;
            if (rl0 >= rows) break;               // rl1 invalid too
            bool v1 = (rl0 + 1) < rows;

            const float* spA = sp0 + (jp * 2) * 128;
            const float* spB = sp0 + (jp * 2 + 1) * 128;

            ull xA[16], xB[16];
            ull aA0 = 0ull, aA1 = 0ull, aB0 = 0ull, aB1 = 0ull;
            #pragma unroll
            for (int i = 0; i < 8; i++) {
                ulonglong2 vA = *(const ulonglong2*)(spA + i * 16 + g * 4);
                ulonglong2 vB = *(const ulonglong2*)(spB + i * 16 + g * 4);
                xA[2*i] = vA.x; xA[2*i+1] = vA.y;
                xB[2*i] = vB.x; xB[2*i+1] = vB.y;
                aA0 = fma2(vA.x, w2[2*i],   aA0);
                aA1 = fma2(vA.y, w2[2*i+1], aA1);
                aB0 = fma2(vB.x, w2[2*i],   aB0);
                aB1 = fma2(vB.y, w2[2*i+1], aB1);
            }
            float fa0, fa1, fa2, fa3, fb0, fb1, fb2, fb3;
            unpack2(aA0, fa0, fa1); unpack2(aA1, fa2, fa3);
            unpack2(aB0, fb0, fb1); unpack2(aB1, fb2, fb3);
            float svA = (fa0 + fa2) + (fa1 + fa3);
            float svB = (fb0 + fb2) + (fb1 + fb3);
            svA += __shfl_xor_sync(0xffffffffu, svA, 1);
            svB += __shfl_xor_sync(0xffffffffu, svB, 1);
            svA += __shfl_xor_sync(0xffffffffu, svA, 2);
            svB += __shfl_xor_sync(0xffffffffu, svB, 2);
            if (!v1) svB = -1e30f;

            float gm = fmaxf(svA, svB);
            if (gm > m) {                         // rare (32-headroom)
                float mn = gm + 32.0f;
                float sc = __expf(m - mn);        // first: exp(-inf)=0
                denom *= sc;
                ull sc2 = pack2(sc, sc);
                #pragma unroll
                for (int i = 0; i < 16; i++) u2[i] = mul2(u2[i], sc2);
                m = mn;
            }
            float pA = __expf(svA - m);
            float pB = __expf(svB - m);           // invalid -> exp(-huge)=0
            denom += pA + pB;
            ull p2A = pack2(pA, pA);
            ull p2B = pack2(pB, pB);
            #pragma unroll
            for (int i = 0; i < 16; i++) {
                u2[i] = fma2(p2A, xA[i], u2[i]);
                u2[i] = fma2(p2B, xB[i], u2[i]);
            }
        }
        ISSUE(s + 4);
    }

    // ---- stage buffers dead: alias for partial merge ----
    __syncthreads();
    float (*sm_u)[8][128] = (float (*)[8][128])sraw;
    {
        float* up = &sm_u[warp][h][0];
        #pragma unroll
        for (int i = 0; i < 8; i++) {
            float f0, f1, f2, f3;
            unpack2(u2[2*i],   f0, f1);
            unpack2(u2[2*i+1], f2, f3);
            *(float4*)(up + i * 16 + g * 4) = make_float4(f0, f1, f2, f3);
        }
        if (g == 0) { sm_m[warp][h] = m; sm_d[warp][h] = denom; }
    }
    __syncthreads();

    if (tid < 8) {
        int hh = tid;
        float mh = -1e30f;
        #pragma unroll
        for (int w = 0; w < 4; w++) mh = fmaxf(mh, sm_m[w][hh]);
        float dt = 0.f;
        #pragma unroll
        for (int w = 0; w < 4; w++) {
            float sc = __expf(sm_m[w][hh] - mh);
            sm_scale[w][hh] = sc;
            dt += sm_d[w][hh] * sc;
        }
        g_pm[pc * 8 + hh] = mh;
        g_pd[pc * 8 + hh] = dt;
    }
    __syncthreads();

    for (int idx = tid; idx < 1024; idx += 128) {
        int hh = idx >> 7, d = idx & 127;
        float acc = 0.f;
        #pragma unroll
        for (int w = 0; w < 4; w++) acc += sm_u[w][hh][d] * sm_scale[w][hh];
        g_pu[pc * 1024 + idx] = acc;
    }
    __syncthreads();

    if (tid == 0) {
        __threadfence();
        s_last = (atomicAdd(&g_cnt[ea], 1) == nact - 1) ? 1 : 0;
    }
    __syncthreads();
    if (!s_last) return;

    float* uf  = (float*)(sraw + 16384);
    float* ctx = (float*)(sraw + 20480);

    if (tid < 8) {
        int hh = tid;
        float M = -1e30f;
        for (int cc = 0; cc < nact; cc++)
            M = fmaxf(M, g_pm[(ea * NC_ + cc) * 8 + hh]);
        float dt = 0.f;
        for (int cc = 0; cc < nact; cc++) {
            float sc = __expf(g_pm[(ea * NC_ + cc) * 8 + hh] - M);
            c_scale[cc][hh] = sc;
            dt += g_pd[(ea * NC_ + cc) * 8 + hh] * sc;
        }
        c_den[hh] = dt;
    }
    __syncthreads();

    for (int idx = tid; idx < 1024; idx += 128) {
        int hh = idx >> 7;
        float acc = 0.f;
        for (int cc = 0; cc < nact; cc++)
            acc += g_pu[(ea * NC_ + cc) * 1024 + idx] * c_scale[cc][hh];
        uf[idx] = acc;
    }
    __syncthreads();

    {
        int hh = tid >> 4;
        float a0 = 0.f, a1 = 0.f;
        #pragma unroll 8
        for (int d = 0; d < 128; d += 2) {
            a0 += uf[hh * 128 + d]     * g_Wv_eff[d * 128 + tid];
            a1 += uf[hh * 128 + d + 1] * g_Wv_eff[(d + 1) * 128 + tid];
        }
        ctx[tid] = (a0 + a1) / c_den[hh] + (float)a * g_Wv_eff[128 * 128 + tid];
    }
    __syncthreads();

    {
        float a0 = 0.f, a1 = 0.f;
        #pragma unroll 8
        for (int j = 0; j < 128; j += 2) {
            a0 += ctx[j]     * __ldg(Wo + j * 128 + tid);
            a1 += ctx[j + 1] * __ldg(Wo + (j + 1) * 128 + tid);
        }
        out[ea * 128 + tid] = a0 + a1;
    }
    #undef ISSUE
}

// ---------------- launch ------------------------------------------------
extern "C" void kernel_launch(void* const* d_in, const int* in_sizes, int n_in,
                              void* d_out, int out_size) {
    const float* gc      = (const float*)d_in[0];
    const float* dep     = (const float*)d_in[1];
    const float* tbd     = (const float*)d_in[2];
    const float* loadv   = (const float*)d_in[3];
    const float* emb     = (const float*)d_in[4];
    const int*   lens    = (const int*)  d_in[5];
    const float* Wq_proj = (const float*)d_in[6];
    const float* Wk_proj = (const float*)d_in[7];
    const float* Wv_proj = (const float*)d_in[8];
    const float* Wq      = (const float*)d_in[9];
    const float* Wk      = (const float*)d_in[10];
    const float* Wv      = (const float*)d_in[11];
    const float* Wo      = (const float*)d_in[12];
    float* out = (float*)d_out;

    setup_eff <<<643, 128>>>(Wq_proj, Wk_proj, Wv_proj, Wq, Wk, Wv);
    setup_wtil<<<EA_, 128>>>(gc, dep, tbd, loadv);
    // 4 sub-launches (1024 CTAs each): puts attn_part in the ncu window
    attn_part <<<1024, 128>>>(emb, lens, Wo, out, 0);
    attn_part <<<1024, 128>>>(emb, lens, Wo, out, 1024);
    attn_part <<<1024, 128>>>(emb, lens, Wo, out, 2048);
    attn_part <<<1024, 128>>>(emb, lens, Wo, out, 3072);
}

// round 15
// speedup vs baseline: 1.2211x; 1.2211x over previous
#include <cuda_runtime.h>
#include <cuda_bf16.h>

#define E_ 64
#define A_ 8
#define L_ 2048
#define D_ 128
#define H_ 8
#define EA_ (E_*A_)
#define CHUNK_ 256
#define NC_ 8

typedef unsigned long long ull;

// ---------------- device scratch ----------------
__device__ float g_Wq_eff[386 * 128];
__device__ float g_Wk_eff[128 * 128];
__device__ float g_Wv_eff[129 * 128];
__device__ float g_wtil [EA_ * H_ * 128];
__device__ float g_pu[EA_ * NC_ * 1024];
__device__ float g_pm[EA_ * NC_ * 8];
__device__ float g_pd[EA_ * NC_ * 8];
__device__ int   g_cnt[EA_];

// ---------------- packed f32x2 helpers ----------
__device__ __forceinline__ ull pack2(float a, float b) {
    ull r; asm("mov.b64 %0, {%1, %2};" : "=l"(r)
               : "r"(__float_as_uint(a)), "r"(__float_as_uint(b)));
    return r;
}
__device__ __forceinline__ void unpack2(ull v, float& a, float& b) {
    unsigned int x, y;
    asm("mov.b64 {%0, %1}, %2;" : "=r"(x), "=r"(y) : "l"(v));
    a = __uint_as_float(x); b = __uint_as_float(y);
}
__device__ __forceinline__ ull fma2(ull a, ull b, ull c) {
    ull d; asm("fma.rn.f32x2 %0, %1, %2, %3;" : "=l"(d) : "l"(a), "l"(b), "l"(c));
    return d;
}
__device__ __forceinline__ ull mul2(ull a, ull b) {
    ull d; asm("mul.rn.f32x2 %0, %1, %2;" : "=l"(d) : "l"(a), "l"(b));
    return d;
}
__device__ __forceinline__ void cp_async16(unsigned int saddr, const void* g) {
    asm volatile("cp.async.cg.shared.global [%0], [%1], 16;" :: "r"(saddr), "l"(g));
}
__device__ __forceinline__ void cp_commit() { asm volatile("cp.async.commit_group;"); }
__device__ __forceinline__ void cp_wait2()  { asm volatile("cp.async.wait_group 2;"); }

// ---------------- setup 1: compose projection matrices -------------------
__global__ void setup_eff(const float* __restrict__ Wq_proj,
                          const float* __restrict__ Wk_proj,
                          const float* __restrict__ Wv_proj,
                          const float* __restrict__ Wq,
                          const float* __restrict__ Wk,
                          const float* __restrict__ Wv) {
    __shared__ float row[128];
    int r = blockIdx.x, t = threadIdx.x;
    const float* proj; const float* W; float* out;
    if (r < 386)      { proj = Wq_proj + r * 128;        W = Wq; out = g_Wq_eff + r * 128; }
    else if (r < 514) { proj = Wk_proj + (r - 386) * 128; W = Wk; out = g_Wk_eff + (r - 386) * 128; }
    else              { proj = Wv_proj + (r - 514) * 128; W = Wv; out = g_Wv_eff + (r - 514) * 128; }
    row[t] = proj[t];
    __syncthreads();
    int h = t >> 4, k = t & 15;
    const float* Wb = W + h * 2048 + k;
    float a0 = 0.f, a1 = 0.f, a2 = 0.f, a3 = 0.f;
    #pragma unroll 8
    for (int m = 0; m < 128; m += 4) {
        a0 += row[m]     * __ldg(Wb + m * 16);
        a1 += row[m + 1] * __ldg(Wb + (m + 1) * 16);
        a2 += row[m + 2] * __ldg(Wb + (m + 2) * 16);
        a3 += row[m + 3] * __ldg(Wb + (m + 3) * 16);
    }
    out[t] = (a0 + a1) + (a2 + a3);
}

// ---------------- setup 2: per-(e,a) query -> w-tilde + cnt reset --------
__global__ void setup_wtil(const float* __restrict__ gc,
                           const float* __restrict__ dep,
                           const float* __restrict__ tbd,
                           const float* __restrict__ loadv) {
    __shared__ float qin[386];
    __shared__ float qh[128];
    int ea = blockIdx.x, t = threadIdx.x;
    int e = ea >> 3, a = ea & 7;
    qin[t]       = gc [e * 128 + t];
    qin[128 + t] = dep[e * 128 + t];
    qin[256 + t] = tbd[e * 128 + t];
    if (t == 0) { qin[384] = loadv[e * 8 + a]; qin[385] = (float)a; g_cnt[ea] = 0; }
    __syncthreads();
    float a0 = 0.f, a1 = 0.f, a2 = 0.f, a3 = 0.f;
    #pragma unroll 4
    for (int j = 0; j < 384; j += 4) {
        a0 += qin[j]     * g_Wq_eff[j * 128 + t];
        a1 += qin[j + 1] * g_Wq_eff[(j + 1) * 128 + t];
        a2 += qin[j + 2] * g_Wq_eff[(j + 2) * 128 + t];
        a3 += qin[j + 3] * g_Wq_eff[(j + 3) * 128 + t];
    }
    a0 += qin[384] * g_Wq_eff[384 * 128 + t];
    a1 += qin[385] * g_Wq_eff[385 * 128 + t];
    qh[t] = (a0 + a1) + (a2 + a3);
    __syncthreads();
    int d = t;
    #pragma unroll
    for (int h = 0; h < 8; h++) {
        float w = 0.f;
        #pragma unroll
        for (int k = 0; k < 16; k++)
            w += qh[h * 16 + k] * g_Wk_eff[d * 128 + h * 16 + k];
        g_wtil[(ea * 8 + h) * 128 + d] = w * 0.25f;
    }
}

// ---------------- attention partial + fused combine ----------------------
// One CTA (128 thr, 4 warps) per (ea, chunk of 256 rows), occupancy 4.
// Warp-private 4-slot cp.async ring; software-pipelined inner loop:
// phase A(s) computes scores/exps from smem (no x reg arrays);
// phase B(s-1) accumulates previous stage's rows (x re-read from its
// still-live slot) weighted by pPrev. A's latency chain hides under B's
// issue work; registers drop ~167 -> ~110 => 16 warps/SM.
__global__ __launch_bounds__(128, 4)
void attn_part(const float* __restrict__ emb,
               const int*   __restrict__ lens,
               const float* __restrict__ Wo,
               float*       __restrict__ out) {
    __shared__ __align__(16) char sraw[32 * 1024];  // 4 warps x 4 slots x 2KB
    __shared__ float sm_m[4][8], sm_d[4][8], sm_scale[4][8];
    __shared__ float c_scale[NC_][8], c_den[8];
    __shared__ int s_last;

    int pc = blockIdx.x;
    int ea = pc >> 3, c = pc & 7;
    int a  = ea & 7;
    int len = lens[ea];
    len = max(1, min(len, L_));
    int c0 = c << 8;
    if (c0 >= len) return;
    int c1 = min(c0 + CHUNK_, len);
    int rows = c1 - c0;
    int nst = (rows + 15) >> 4;
    int nact = min(NC_, (len + CHUNK_ - 1) >> 8);

    int tid  = threadIdx.x;
    int warp = tid >> 5, lane = tid & 31;
    int h = lane >> 2, g = lane & 3;

    float* wbuf = (float*)(sraw + warp * 8192);      // 4 x 2KB slots
    unsigned int sb = (unsigned int)__cvta_generic_to_shared(wbuf);
    const char* base = (const char*)emb + (size_t)ea * (L_ * 512);

    #define ISSUE(S) do {                                                    \
        int s_ = (S);                                                        \
        if (s_ < nst) {                                                      \
            unsigned int sb_ = sb + (unsigned int)((s_ & 3) * 2048);         \
            _Pragma("unroll")                                                \
            for (int j_ = 0; j_ < 4; j_++) {                                 \
                int r_ = min(c0 + s_ * 16 + warp * 4 + j_, c1 - 1);          \
                cp_async16(sb_ + j_ * 512 + lane * 16,                       \
                           base + (size_t)r_ * 512 + lane * 16);             \
            }                                                                \
        }                                                                    \
        cp_commit();                                                         \
    } while (0)

    // accumulate 4 rows from SLOT with weights P[0..3]
    #define PHASE_B(SLOT, P) do {                                            \
        const float* bp_ = wbuf + ((SLOT) << 9);                             \
        _Pragma("unroll")                                                    \
        for (int j_ = 0; j_ < 4; j_++) {                                     \
            ull pj_ = pack2((P)[j_], (P)[j_]);                               \
            const float* sp_ = bp_ + j_ * 128;                               \
            _Pragma("unroll")                                                \
            for (int i_ = 0; i_ < 8; i_++) {                                 \
                ulonglong2 v_ = *(const ulonglong2*)(sp_ + i_ * 16 + g * 4); \
                u2[2*i_]   = fma2(pj_, v_.x, u2[2*i_]);                      \
                u2[2*i_+1] = fma2(pj_, v_.y, u2[2*i_+1]);                    \
            }                                                                \
        }                                                                    \
    } while (0)

    ull w2[16], u2[16];
    {
        const float* wb = g_wtil + (ea * 8 + h) * 128;
        #pragma unroll
        for (int i = 0; i < 8; i++) {
            ulonglong2 v = *(const ulonglong2*)(wb + i * 16 + g * 4);
            w2[2*i] = v.x; w2[2*i+1] = v.y;
        }
    }
    #pragma unroll
    for (int i = 0; i < 16; i++) u2[i] = 0ull;

    float m = -1e30f;
    float denom = 0.f;
    float pPrev[4] = {0.f, 0.f, 0.f, 0.f};

    ISSUE(0); ISSUE(1); ISSUE(2);

    for (int s = 0; s < nst; s++) {
        cp_wait2();                               // slot s ready
        const float* sp0 = wbuf + ((s & 3) << 9);
        int rb = s * 16 + warp * 4;

        // ---- phase A(s): scores for this stage's 4 rows ----
        ull sa[4][2];
        #pragma unroll
        for (int j = 0; j < 4; j++) { sa[j][0] = 0ull; sa[j][1] = 0ull; }
        #pragma unroll
        for (int i = 0; i < 8; i++) {
            #pragma unroll
            for (int j = 0; j < 4; j++) {
                ulonglong2 v = *(const ulonglong2*)(sp0 + j * 128 + i * 16 + g * 4);
                sa[j][0] = fma2(v.x, w2[2*i],   sa[j][0]);
                sa[j][1] = fma2(v.y, w2[2*i+1], sa[j][1]);
            }
        }
        float sv[4];
        #pragma unroll
        for (int j = 0; j < 4; j++) {
            float f0, f1, f2, f3;
            unpack2(sa[j][0], f0, f1);
            unpack2(sa[j][1], f2, f3);
            sv[j] = (f0 + f2) + (f1 + f3);
        }
        #pragma unroll
        for (int j = 0; j < 4; j++)
            sv[j] += __shfl_xor_sync(0xffffffffu, sv[j], 1);
        #pragma unroll
        for (int j = 0; j < 4; j++)
            sv[j] += __shfl_xor_sync(0xffffffffu, sv[j], 2);
        #pragma unroll
        for (int j = 0; j < 4; j++)
            if (rb + j >= rows) sv[j] = -1e30f;

        float gm = fmaxf(fmaxf(sv[0], sv[1]), fmaxf(sv[2], sv[3]));
        if (gm > m) {                             // rare (32-headroom)
            float mn = gm + 32.0f;
            float sc = __expf(m - mn);            // first: ~0
            denom *= sc;
            ull sc2 = pack2(sc, sc);
            #pragma unroll
            for (int i = 0; i < 16; i++) u2[i] = mul2(u2[i], sc2);
            #pragma unroll
            for (int j = 0; j < 4; j++) pPrev[j] *= sc;   // keep delayed p's consistent
            m = mn;
        }
        float pNew[4];
        #pragma unroll
        for (int j = 0; j < 4; j++) pNew[j] = __expf(sv[j] - m);
        denom += (pNew[0] + pNew[1]) + (pNew[2] + pNew[3]);

        // ---- phase B(s-1): accumulate previous stage (slot (s-1)&3) ----
        if (s > 0) PHASE_B((s - 1) & 3, pPrev);
        #pragma unroll
        for (int j = 0; j < 4; j++) pPrev[j] = pNew[j];

        ISSUE(s + 3);                              // writes (s+3)&3 = (s-1)&3 (B done)
    }
    // final phase B for last stage
    PHASE_B((nst - 1) & 3, pPrev);

    // ---- stage buffers dead: alias for partial merge ----
    __syncthreads();
    float (*sm_u)[8][128] = (float (*)[8][128])sraw;
    {
        float* up = &sm_u[warp][h][0];
        #pragma unroll
        for (int i = 0; i < 8; i++) {
            float f0, f1, f2, f3;
            unpack2(u2[2*i],   f0, f1);
            unpack2(u2[2*i+1], f2, f3);
            *(float4*)(up + i * 16 + g * 4) = make_float4(f0, f1, f2, f3);
        }
        if (g == 0) { sm_m[warp][h] = m; sm_d[warp][h] = denom; }
    }
    __syncthreads();

    if (tid < 8) {
        int hh = tid;
        float mh = -1e30f;
        #pragma unroll
        for (int w = 0; w < 4; w++) mh = fmaxf(mh, sm_m[w][hh]);
        float dt = 0.f;
        #pragma unroll
        for (int w = 0; w < 4; w++) {
            float sc = __expf(sm_m[w][hh] - mh);
            sm_scale[w][hh] = sc;
            dt += sm_d[w][hh] * sc;
        }
        g_pm[pc * 8 + hh] = mh;
        g_pd[pc * 8 + hh] = dt;
    }
    __syncthreads();

    for (int idx = tid; idx < 1024; idx += 128) {
        int hh = idx >> 7, d = idx & 127;
        float acc = 0.f;
        #pragma unroll
        for (int w = 0; w < 4; w++) acc += sm_u[w][hh][d] * sm_scale[w][hh];
        g_pu[pc * 1024 + idx] = acc;
    }
    __syncthreads();

    if (tid == 0) {
        __threadfence();
        s_last = (atomicAdd(&g_cnt[ea], 1) == nact - 1) ? 1 : 0;
    }
    __syncthreads();
    if (!s_last) return;

    float* uf  = (float*)(sraw + 16384);
    float* ctx = (float*)(sraw + 20480);

    if (tid < 8) {
        int hh = tid;
        float M = -1e30f;
        for (int cc = 0; cc < nact; cc++)
            M = fmaxf(M, g_pm[(ea * NC_ + cc) * 8 + hh]);
        float dt = 0.f;
        for (int cc = 0; cc < nact; cc++) {
            float sc = __expf(g_pm[(ea * NC_ + cc) * 8 + hh] - M);
            c_scale[cc][hh] = sc;
            dt += g_pd[(ea * NC_ + cc) * 8 + hh] * sc;
        }
        c_den[hh] = dt;
    }
    __syncthreads();

    for (int idx = tid; idx < 1024; idx += 128) {
        int hh = idx >> 7;
        float acc = 0.f;
        for (int cc = 0; cc < nact; cc++)
            acc += g_pu[(ea * NC_ + cc) * 1024 + idx] * c_scale[cc][hh];
        uf[idx] = acc;
    }
    __syncthreads();

    {
        int hh = tid >> 4;
        float a0 = 0.f, a1 = 0.f;
        #pragma unroll 8
        for (int d = 0; d < 128; d += 2) {
            a0 += uf[hh * 128 + d]     * g_Wv_eff[d * 128 + tid];
            a1 += uf[hh * 128 + d + 1] * g_Wv_eff[(d + 1) * 128 + tid];
        }
        ctx[tid] = (a0 + a1) / c_den[hh] + (float)a * g_Wv_eff[128 * 128 + tid];
    }
    __syncthreads();

    {
        float a0 = 0.f, a1 = 0.f;
        #pragma unroll 8
        for (int j = 0; j < 128; j += 2) {
            a0 += ctx[j]     * __ldg(Wo + j * 128 + tid);
            a1 += ctx[j + 1] * __ldg(Wo + (j + 1) * 128 + tid);
        }
        out[ea * 128 + tid] = a0 + a1;
    }
    #undef ISSUE
    #undef PHASE_B
}

// ---------------- launch ------------------------------------------------
extern "C" void kernel_launch(void* const* d_in, const int* in_sizes, int n_in,
                              void* d_out, int out_size) {
    const float* gc      = (const float*)d_in[0];
    const float* dep     = (const float*)d_in[1];
    const float* tbd     = (const float*)d_in[2];
    const float* loadv   = (const float*)d_in[3];
    const float* emb     = (const float*)d_in[4];
    const int*   lens    = (const int*)  d_in[5];
    const float* Wq_proj = (const float*)d_in[6];
    const float* Wk_proj = (const float*)d_in[7];
    const float* Wv_proj = (const float*)d_in[8];
    const float* Wq      = (const float*)d_in[9];
    const float* Wk      = (const float*)d_in[10];
    const float* Wv      = (const float*)d_in[11];
    const float* Wo      = (const float*)d_in[12];
    float* out = (float*)d_out;

    setup_eff <<<643, 128>>>(Wq_proj, Wk_proj, Wv_proj, Wq, Wk, Wv);
    setup_wtil<<<EA_, 128>>>(gc, dep, tbd, loadv);
    attn_part <<<EA_ * NC_, 128>>>(emb, lens, Wo, out);
}

// round 16
// speedup vs baseline: 1.5282x; 1.2515x over previous
#include <cuda_runtime.h>
#include <cuda_bf16.h>

#define E_ 64
#define A_ 8
#define L_ 2048
#define D_ 128
#define H_ 8
#define EA_ (E_*A_)
#define CHUNK_ 256
#define NC_ 8

typedef unsigned long long ull;

// ---------------- device scratch ----------------
__device__ float g_Wq_eff[386 * 128];
__device__ float g_Wk_eff[128 * 128];
__device__ float g_Wv_eff[129 * 128];
__device__ float g_wtil [EA_ * H_ * 128];
__device__ float g_pu[EA_ * NC_ * 1024];
__device__ float g_pm[EA_ * NC_ * 8];
__device__ float g_pd[EA_ * NC_ * 8];
__device__ int   g_cnt[EA_];

// ---------------- packed f32x2 helpers ----------
__device__ __forceinline__ ull pack2(float a, float b) {
    ull r; asm("mov.b64 %0, {%1, %2};" : "=l"(r)
               : "r"(__float_as_uint(a)), "r"(__float_as_uint(b)));
    return r;
}
__device__ __forceinline__ void unpack2(ull v, float& a, float& b) {
    unsigned int x, y;
    asm("mov.b64 {%0, %1}, %2;" : "=r"(x), "=r"(y) : "l"(v));
    a = __uint_as_float(x); b = __uint_as_float(y);
}
__device__ __forceinline__ ull fma2(ull a, ull b, ull c) {
    ull d; asm("fma.rn.f32x2 %0, %1, %2, %3;" : "=l"(d) : "l"(a), "l"(b), "l"(c));
    return d;
}
__device__ __forceinline__ ull mul2(ull a, ull b) {
    ull d; asm("mul.rn.f32x2 %0, %1, %2;" : "=l"(d) : "l"(a), "l"(b));
    return d;
}
__device__ __forceinline__ void cp_async16(unsigned int saddr, const void* g) {
    asm volatile("cp.async.cg.shared.global [%0], [%1], 16;" :: "r"(saddr), "l"(g));
}
__device__ __forceinline__ void cp_commit() { asm volatile("cp.async.commit_group;"); }
__device__ __forceinline__ void cp_wait3()  { asm volatile("cp.async.wait_group 3;"); }

// per-row 512B XOR swizzle: injects bits [8:7] into [5:4] (16B granularity)
#define SWZ_(o) ((o) ^ (((o) & 0x180) >> 3))

// ---------------- setup 1: compose projection matrices -------------------
__global__ void setup_eff(const float* __restrict__ Wq_proj,
                          const float* __restrict__ Wk_proj,
                          const float* __restrict__ Wv_proj,
                          const float* __restrict__ Wq,
                          const float* __restrict__ Wk,
                          const float* __restrict__ Wv) {
    __shared__ float row[128];
    int r = blockIdx.x, t = threadIdx.x;
    const float* proj; const float* W; float* out;
    if (r < 386)      { proj = Wq_proj + r * 128;        W = Wq; out = g_Wq_eff + r * 128; }
    else if (r < 514) { proj = Wk_proj + (r - 386) * 128; W = Wk; out = g_Wk_eff + (r - 386) * 128; }
    else              { proj = Wv_proj + (r - 514) * 128; W = Wv; out = g_Wv_eff + (r - 514) * 128; }
    row[t] = proj[t];
    __syncthreads();
    int h = t >> 4, k = t & 15;
    const float* Wb = W + h * 2048 + k;
    float a0 = 0.f, a1 = 0.f, a2 = 0.f, a3 = 0.f;
    #pragma unroll 8
    for (int m = 0; m < 128; m += 4) {
        a0 += row[m]     * __ldg(Wb + m * 16);
        a1 += row[m + 1] * __ldg(Wb + (m + 1) * 16);
        a2 += row[m + 2] * __ldg(Wb + (m + 2) * 16);
        a3 += row[m + 3] * __ldg(Wb + (m + 3) * 16);
    }
    out[t] = (a0 + a1) + (a2 + a3);
}

// ---------------- setup 2: per-(e,a) query -> w-tilde + cnt reset --------
__global__ void setup_wtil(const float* __restrict__ gc,
                           const float* __restrict__ dep,
                           const float* __restrict__ tbd,
                           const float* __restrict__ loadv) {
    __shared__ float qin[386];
    __shared__ float qh[128];
    int ea = blockIdx.x, t = threadIdx.x;
    int e = ea >> 3, a = ea & 7;
    qin[t]       = gc [e * 128 + t];
    qin[128 + t] = dep[e * 128 + t];
    qin[256 + t] = tbd[e * 128 + t];
    if (t == 0) { qin[384] = loadv[e * 8 + a]; qin[385] = (float)a; g_cnt[ea] = 0; }
    __syncthreads();
    float a0 = 0.f, a1 = 0.f, a2 = 0.f, a3 = 0.f;
    #pragma unroll 4
    for (int j = 0; j < 384; j += 4) {
        a0 += qin[j]     * g_Wq_eff[j * 128 + t];
        a1 += qin[j + 1] * g_Wq_eff[(j + 1) * 128 + t];
        a2 += qin[j + 2] * g_Wq_eff[(j + 2) * 128 + t];
        a3 += qin[j + 3] * g_Wq_eff[(j + 3) * 128 + t];
    }
    a0 += qin[384] * g_Wq_eff[384 * 128 + t];
    a1 += qin[385] * g_Wq_eff[385 * 128 + t];
    qh[t] = (a0 + a1) + (a2 + a3);
    __syncthreads();
    int d = t;
    #pragma unroll
    for (int h = 0; h < 8; h++) {
        float w = 0.f;
        #pragma unroll
        for (int k = 0; k < 16; k++)
            w += qh[h * 16 + k] * g_Wk_eff[d * 128 + h * 16 + k];
        g_wtil[(ea * 8 + h) * 128 + d] = w * 0.25f;
    }
}

// ---------------- attention partial + fused combine ----------------------
// One CTA (128 thr, 4 warps) per (ea, chunk of 256 rows), occupancy 3.
// alpha=2 lane layout: hg = lane>>3 owns heads {2hg, 2hg+1};
// dg = lane&7 owns d-slice [dg*16, dg*16+16). Per row each lane reads only
// its 64B of x (2KB delivered/row instead of 4KB), reduces scores over the
// 8 dg-lanes (3 butterflies), and accumulates its own 2 heads — no gather.
// Per-row 512B XOR swizzle keeps the dg-strided reads bank-conflict-free.
__global__ __launch_bounds__(128, 3)
void attn_part(const float* __restrict__ emb,
               const int*   __restrict__ lens,
               const float* __restrict__ Wo,
               float*       __restrict__ out) {
    __shared__ __align__(16) char sraw[32 * 1024];  // 4 warps x 4 slots x 2KB
    __shared__ float sm_m[4][8], sm_d[4][8], sm_scale[4][8];
    __shared__ float c_scale[NC_][8], c_den[8];
    __shared__ int s_last;

    int pc = blockIdx.x;
    int ea = pc >> 3, c = pc & 7;
    int a  = ea & 7;
    int len = lens[ea];
    len = max(1, min(len, L_));
    int c0 = c << 8;
    if (c0 >= len) return;
    int c1 = min(c0 + CHUNK_, len);
    int rows = c1 - c0;
    int nst = (rows + 15) >> 4;
    int nact = min(NC_, (len + CHUNK_ - 1) >> 8);

    int tid  = threadIdx.x;
    int warp = tid >> 5, lane = tid & 31;
    int hg = lane >> 3, dg = lane & 7;

    char* wbuf = sraw + warp * 8192;                 // 4 x 2KB slots
    unsigned int sb = (unsigned int)__cvta_generic_to_shared(wbuf);
    const char* base = (const char*)emb + (size_t)ea * (L_ * 512);

    // swizzled write offset for this lane's 16B chunk within a row
    int swz_wr = SWZ_(lane * 16);
    // swizzled read offsets for this lane's 4 chunks (dg*64 + q*16)
    int sw0 = SWZ_(dg * 64 + 0);
    int sw1 = SWZ_(dg * 64 + 16);
    int sw2 = SWZ_(dg * 64 + 32);
    int sw3 = SWZ_(dg * 64 + 48);

    #define ISSUE(S) do {                                                    \
        int s_ = (S);                                                        \
        if (s_ < nst) {                                                      \
            unsigned int sb_ = sb + (unsigned int)((s_ & 3) * 2048);         \
            _Pragma("unroll")                                                \
            for (int j_ = 0; j_ < 4; j_++) {                                 \
                int r_ = min(c0 + s_ * 16 + warp * 4 + j_, c1 - 1);          \
                cp_async16(sb_ + j_ * 512 + swz_wr,                          \
                           base + (size_t)r_ * 512 + lane * 16);             \
            }                                                                \
        }                                                                    \
        cp_commit();                                                         \
    } while (0)

    // load row of 16B pieces from a swizzled smem row
    #define LOADX(X, ROWP) do {                                              \
        ulonglong2 v0_ = *(const ulonglong2*)((ROWP) + sw0);                 \
        ulonglong2 v1_ = *(const ulonglong2*)((ROWP) + sw1);                 \
        ulonglong2 v2_ = *(const ulonglong2*)((ROWP) + sw2);                 \
        ulonglong2 v3_ = *(const ulonglong2*)((ROWP) + sw3);                 \
        (X)[0] = v0_.x; (X)[1] = v0_.y; (X)[2] = v1_.x; (X)[3] = v1_.y;      \
        (X)[4] = v2_.x; (X)[5] = v2_.y; (X)[6] = v3_.x; (X)[7] = v3_.y;      \
    } while (0)

    // w2[t*8 + 0..7] = w-tilde of head 2hg+t at this lane's 16-float slice
    ull w2[16], u2[16];
    {
        #pragma unroll
        for (int t = 0; t < 2; t++) {
            const char* wb = (const char*)(g_wtil + (ea * 8 + 2 * hg + t) * 128)
                           + dg * 64;
            #pragma unroll
            for (int q = 0; q < 4; q++) {
                ulonglong2 v = *(const ulonglong2*)(wb + q * 16);
                w2[t * 8 + 2 * q] = v.x; w2[t * 8 + 2 * q + 1] = v.y;
            }
        }
    }
    #pragma unroll
    for (int i = 0; i < 16; i++) u2[i] = 0ull;

    float m = -1e30f;
    float d0 = 0.f, d1 = 0.f;   // denoms for heads 2hg, 2hg+1

    ISSUE(0); ISSUE(1); ISSUE(2); ISSUE(3);

    for (int s = 0; s < nst; s++) {
        cp_wait3();
        const char* sp0 = wbuf + ((s & 3) << 11);
        int rb = s * 16 + warp * 4;

        #pragma unroll
        for (int jp = 0; jp < 2; jp++) {          // two pairs of rows
            int rl0 = rb + jp * 2;
            if (rl0 >= rows) break;               // rl1 invalid too
            bool v1 = (rl0 + 1) < rows;

            const char* rA = sp0 + (jp * 2) * 512;
            const char* rB = rA + 512;

            ull xA[8], xB[8];
            LOADX(xA, rA);
            LOADX(xB, rB);

            // 4 independent 8-deep score chains (2 rows x 2 heads)
            ull aA0 = 0ull, aA1 = 0ull, aB0 = 0ull, aB1 = 0ull;
            #pragma unroll
            for (int i = 0; i < 8; i++) {
                aA0 = fma2(xA[i], w2[i],     aA0);
                aA1 = fma2(xA[i], w2[8 + i], aA1);
                aB0 = fma2(xB[i], w2[i],     aB0);
                aB1 = fma2(xB[i], w2[8 + i], aB1);
            }
            float svA0, svA1, svB0, svB1;
            { float lo, hi; unpack2(aA0, lo, hi); svA0 = lo + hi; }
            { float lo, hi; unpack2(aA1, lo, hi); svA1 = lo + hi; }
            { float lo, hi; unpack2(aB0, lo, hi); svB0 = lo + hi; }
            { float lo, hi; unpack2(aB1, lo, hi); svB1 = lo + hi; }

            // reduce over the 8 dg-lanes (batched butterflies)
            svA0 += __shfl_xor_sync(0xffffffffu, svA0, 1);
            svA1 += __shfl_xor_sync(0xffffffffu, svA1, 1);
            svB0 += __shfl_xor_sync(0xffffffffu, svB0, 1);
            svB1 += __shfl_xor_sync(0xffffffffu, svB1, 1);
            svA0 += __shfl_xor_sync(0xffffffffu, svA0, 2);
            svA1 += __shfl_xor_sync(0xffffffffu, svA1, 2);
            svB0 += __shfl_xor_sync(0xffffffffu, svB0, 2);
            svB1 += __shfl_xor_sync(0xffffffffu, svB1, 2);
            svA0 += __shfl_xor_sync(0xffffffffu, svA0, 4);
            svA1 += __shfl_xor_sync(0xffffffffu, svA1, 4);
            svB0 += __shfl_xor_sync(0xffffffffu, svB0, 4);
            svB1 += __shfl_xor_sync(0xffffffffu, svB1, 4);
            if (!v1) { svB0 = -1e30f; svB1 = -1e30f; }

            float gm = fmaxf(fmaxf(svA0, svA1), fmaxf(svB0, svB1));
            if (gm > m) {                         // rare (32-headroom)
                float mn = gm + 32.0f;
                float sc = __expf(m - mn);        // first: exp(-inf)=0
                d0 *= sc; d1 *= sc;
                ull sc2 = pack2(sc, sc);
                #pragma unroll
                for (int i = 0; i < 16; i++) u2[i] = mul2(u2[i], sc2);
                m = mn;
            }
            float pA0 = __expf(svA0 - m);
            float pA1 = __expf(svA1 - m);
            float pB0 = __expf(svB0 - m);         // invalid -> 0
            float pB1 = __expf(svB1 - m);
            d0 += pA0 + pB0;
            d1 += pA1 + pB1;
            ull qA0 = pack2(pA0, pA0), qA1 = pack2(pA1, pA1);
            ull qB0 = pack2(pB0, pB0), qB1 = pack2(pB1, pB1);
            #pragma unroll
            for (int i = 0; i < 8; i++) {
                u2[i]     = fma2(qA0, xA[i], u2[i]);
                u2[i]     = fma2(qB0, xB[i], u2[i]);
                u2[8 + i] = fma2(qA1, xA[i], u2[8 + i]);
                u2[8 + i] = fma2(qB1, xB[i], u2[8 + i]);
            }
        }
        ISSUE(s + 4);
    }

    // ---- stage buffers dead: alias for partial merge ----
    __syncthreads();
    float (*sm_u)[8][128] = (float (*)[8][128])sraw;
    {
        float* up0 = &sm_u[warp][2 * hg][dg * 16];
        float* up1 = &sm_u[warp][2 * hg + 1][dg * 16];
        #pragma unroll
        for (int q = 0; q < 4; q++) {
            float f0, f1, f2, f3;
            unpack2(u2[2 * q],     f0, f1);
            unpack2(u2[2 * q + 1], f2, f3);
            *(float4*)(up0 + q * 4) = make_float4(f0, f1, f2, f3);
            unpack2(u2[8 + 2 * q],     f0, f1);
            unpack2(u2[8 + 2 * q + 1], f2, f3);
            *(float4*)(up1 + q * 4) = make_float4(f0, f1, f2, f3);
        }
        if (dg == 0) {
            sm_m[warp][2 * hg] = m;     sm_m[warp][2 * hg + 1] = m;
            sm_d[warp][2 * hg] = d0;    sm_d[warp][2 * hg + 1] = d1;
        }
    }
    __syncthreads();

    if (tid < 8) {
        int hh = tid;
        float mh = -1e30f;
        #pragma unroll
        for (int w = 0; w < 4; w++) mh = fmaxf(mh, sm_m[w][hh]);
        float dt = 0.f;
        #pragma unroll
        for (int w = 0; w < 4; w++) {
            float sc = __expf(sm_m[w][hh] - mh);
            sm_scale[w][hh] = sc;
            dt += sm_d[w][hh] * sc;
        }
        g_pm[pc * 8 + hh] = mh;
        g_pd[pc * 8 + hh] = dt;
    }
    __syncthreads();

    for (int idx = tid; idx < 1024; idx += 128) {
        int hh = idx >> 7, d = idx & 127;
        float acc = 0.f;
        #pragma unroll
        for (int w = 0; w < 4; w++) acc += sm_u[w][hh][d] * sm_scale[w][hh];
        g_pu[pc * 1024 + idx] = acc;
    }
    __syncthreads();

    if (tid == 0) {
        __threadfence();
        s_last = (atomicAdd(&g_cnt[ea], 1) == nact - 1) ? 1 : 0;
    }
    __syncthreads();
    if (!s_last) return;

    float* uf  = (float*)(sraw + 16384);
    float* ctx = (float*)(sraw + 20480);

    if (tid < 8) {
        int hh = tid;
        float M = -1e30f;
        for (int cc = 0; cc < nact; cc++)
            M = fmaxf(M, g_pm[(ea * NC_ + cc) * 8 + hh]);
        float dt = 0.f;
        for (int cc = 0; cc < nact; cc++) {
            float sc = __expf(g_pm[(ea * NC_ + cc) * 8 + hh] - M);
            c_scale[cc][hh] = sc;
            dt += g_pd[(ea * NC_ + cc) * 8 + hh] * sc;
        }
        c_den[hh] = dt;
    }
    __syncthreads();

    for (int idx = tid; idx < 1024; idx += 128) {
        int hh = idx >> 7;
        float acc = 0.f;
        for (int cc = 0; cc < nact; cc++)
            acc += g_pu[(ea * NC_ + cc) * 1024 + idx] * c_scale[cc][hh];
        uf[idx] = acc;
    }
    __syncthreads();

    {
        int hh = tid >> 4;
        float a0 = 0.f, a1 = 0.f;
        #pragma unroll 8
        for (int d = 0; d < 128; d += 2) {
            a0 += uf[hh * 128 + d]     * g_Wv_eff[d * 128 + tid];
            a1 += uf[hh * 128 + d + 1] * g_Wv_eff[(d + 1) * 128 + tid];
        }
        ctx[tid] = (a0 + a1) / c_den[hh] + (float)a * g_Wv_eff[128 * 128 + tid];
    }
    __syncthreads();

    {
        float a0 = 0.f, a1 = 0.f;
        #pragma unroll 8
        for (int j = 0; j < 128; j += 2) {
            a0 += ctx[j]     * __ldg(Wo + j * 128 + tid);
            a1 += ctx[j + 1] * __ldg(Wo + (j + 1) * 128 + tid);
        }
        out[ea * 128 + tid] = a0 + a1;
    }
    #undef ISSUE
    #undef LOADX
}

// ---------------- launch ------------------------------------------------
extern "C" void kernel_launch(void* const* d_in, const int* in_sizes, int n_in,
                              void* d_out, int out_size) {
    const float* gc      = (const float*)d_in[0];
    const float* dep     = (const float*)d_in[1];
    const float* tbd     = (const float*)d_in[2];
    const float* loadv   = (const float*)d_in[3];
    const float* emb     = (const float*)d_in[4];
    const int*   lens    = (const int*)  d_in[5];
    const float* Wq_proj = (const float*)d_in[6];
    const float* Wk_proj = (const float*)d_in[7];
    const float* Wv_proj = (const float*)d_in[8];
    const float* Wq      = (const float*)d_in[9];
    const float* Wk      = (const float*)d_in[10];
    const float* Wv      = (const float*)d_in[11];
    const float* Wo      = (const float*)d_in[12];
    float* out = (float*)d_out;

    setup_eff <<<643, 128>>>(Wq_proj, Wk_proj, Wv_proj, Wq, Wk, Wv);
    setup_wtil<<<EA_, 128>>>(gc, dep, tbd, loadv);
    attn_part <<<EA_ * NC_, 128>>>(emb, lens, Wo, out);
}